// round 3
// baseline (speedup 1.0000x reference)
#include <cuda_runtime.h>
#include <math.h>
#include <float.h>

// ---------------- problem constants ----------------
#define BB     8
#define LSEQ   4096
#define DMOD   512
#define DFF    2048
#define NH     8
#define DH     64
#define SKN    128
#define TOPU   128
#define ROWS   (BB*LSEQ)          // 32768
#define BHN    (BB*NH)            // 64

// ---------------- scratch (device globals; no cudaMalloc allowed) ----------------
__device__ float g_Q[(size_t)ROWS*DMOD];     // [B,H,L,DH]
__device__ float g_K[(size_t)ROWS*DMOD];     // [B,H,L,DH]
__device__ float g_V[(size_t)ROWS*DMOD];     // [B,H,L,DH]
__device__ float g_ctx[(size_t)ROWS*DMOD];   // [B,L,D]
__device__ float g_y[(size_t)ROWS*DMOD];     // x + attn_out
__device__ float g_x1[(size_t)ROWS*DMOD];    // LN1 output
__device__ float g_ff[(size_t)ROWS*DFF];     // relu(x1@W1f+b1f)
__device__ float g_y2[(size_t)ROWS*DMOD];    // x1 + ffn
__device__ float g_M[BHN*LSEQ];
__device__ int   g_top[BHN*TOPU];
__device__ float g_meanV[BHN*DH];

// ---------------- packed f32x2 helpers ----------------
__device__ __forceinline__ unsigned long long pack2(float x) {
    unsigned long long r;
    asm("mov.b64 %0, {%1, %1};" : "=l"(r) : "f"(x));
    return r;
}
__device__ __forceinline__ void fma2(unsigned long long& d,
                                     unsigned long long a,
                                     unsigned long long b) {
    asm("fma.rn.f32x2 %0, %1, %2, %0;" : "+l"(d) : "l"(a), "l"(b));
}

// ---------------- SGEMM: C[M,N] = A[M,K] @ B[K,N] + bias (+res) (relu) ----------
// PERM=1: write C in [B,H,L,DH] head-split layout (N must be 512).
template<int PERM, int RELU, int RES>
__global__ void __launch_bounds__(256, 2)
sgemm_kernel(const float* __restrict__ A, const float* __restrict__ Bm,
             const float* __restrict__ bias, const float* __restrict__ res,
             float* __restrict__ C, int M, int N, int K, int Lp)
{
    __shared__ float As[16][128];
    __shared__ float Bs[16][128];

    const int tid = threadIdx.x;
    const int tr  = tid >> 4;      // 0..15
    const int tc  = tid & 15;      // 0..15
    const int bm  = blockIdx.y * 128;
    const int bn  = blockIdx.x * 128;

    unsigned long long acc[8][4];
    #pragma unroll
    for (int m = 0; m < 8; m++)
        #pragma unroll
        for (int n = 0; n < 4; n++) acc[m][n] = 0ull;

    const float* Ab = A + (size_t)bm * K;
    const float* Bb = Bm + bn;

    for (int kt = 0; kt < K; kt += 16) {
        // load A tile (128x16), store transposed As[k][m]
        #pragma unroll
        for (int i = 0; i < 2; i++) {
            int id = tid * 2 + i;
            int r  = id >> 2;
            int c4 = (id & 3) * 4;
            float4 v = *(const float4*)(Ab + (size_t)r * K + kt + c4);
            As[c4 + 0][r] = v.x; As[c4 + 1][r] = v.y;
            As[c4 + 2][r] = v.z; As[c4 + 3][r] = v.w;
        }
        // load B tile (16x128)
        #pragma unroll
        for (int i = 0; i < 2; i++) {
            int id = tid * 2 + i;
            int r  = id >> 5;
            int c4 = (id & 31) * 4;
            *(float4*)&Bs[r][c4] = *(const float4*)(Bb + (size_t)(kt + r) * N + c4);
        }
        __syncthreads();

        #pragma unroll
        for (int kk = 0; kk < 16; kk++) {
            float4 a0 = *(float4*)&As[kk][tr * 8];
            float4 a1 = *(float4*)&As[kk][tr * 8 + 4];
            float4 b0 = *(float4*)&Bs[kk][tc * 8];
            float4 b1 = *(float4*)&Bs[kk][tc * 8 + 4];

            unsigned long long av[8];
            av[0] = pack2(a0.x); av[1] = pack2(a0.y);
            av[2] = pack2(a0.z); av[3] = pack2(a0.w);
            av[4] = pack2(a1.x); av[5] = pack2(a1.y);
            av[6] = pack2(a1.z); av[7] = pack2(a1.w);

            unsigned long long bv[4];
            bv[0] = ((const unsigned long long*)&b0)[0];
            bv[1] = ((const unsigned long long*)&b0)[1];
            bv[2] = ((const unsigned long long*)&b1)[0];
            bv[3] = ((const unsigned long long*)&b1)[1];

            #pragma unroll
            for (int m = 0; m < 8; m++)
                #pragma unroll
                for (int n = 0; n < 4; n++)
                    fma2(acc[m][n], av[m], bv[n]);
        }
        __syncthreads();
    }

    // epilogue
    const int c0 = bn + tc * 8;
    float4 bia0 = *(const float4*)(bias + c0);
    float4 bia1 = *(const float4*)(bias + c0 + 4);

    #pragma unroll
    for (int m = 0; m < 8; m++) {
        int r = bm + tr * 8 + m;
        float o[8];
        #pragma unroll
        for (int n = 0; n < 4; n++) {
            float2 f = *(float2*)&acc[m][n];
            o[2 * n]     = f.x;
            o[2 * n + 1] = f.y;
        }
        o[0] += bia0.x; o[1] += bia0.y; o[2] += bia0.z; o[3] += bia0.w;
        o[4] += bia1.x; o[5] += bia1.y; o[6] += bia1.z; o[7] += bia1.w;
        if (RES) {
            const float* rp = res + (size_t)r * N + c0;
            float4 r0 = *(const float4*)rp;
            float4 r1 = *(const float4*)(rp + 4);
            o[0] += r0.x; o[1] += r0.y; o[2] += r0.z; o[3] += r0.w;
            o[4] += r1.x; o[5] += r1.y; o[6] += r1.z; o[7] += r1.w;
        }
        if (RELU) {
            #pragma unroll
            for (int j = 0; j < 8; j++) o[j] = fmaxf(o[j], 0.0f);
        }
        float4 w0 = make_float4(o[0], o[1], o[2], o[3]);
        float4 w1 = make_float4(o[4], o[5], o[6], o[7]);
        if (PERM) {
            int b = r / Lp, l = r - b * Lp;
            int h = c0 >> 6, d = c0 & 63;
            float* cp = C + (((size_t)(b * NH + h) * Lp + l) << 6) + d;
            *(float4*)cp = w0;
            *(float4*)(cp + 4) = w1;
        } else {
            float* cp = C + (size_t)r * N + c0;
            *(float4*)cp = w0;
            *(float4*)(cp + 4) = w1;
        }
    }
}

// ---------------- sampled scores: M[bh,l] = max_s(q.ks) - mean_s(q.ks) -----------
__global__ void k_sample_scores(const long long* __restrict__ sidx)
{
    __shared__ float Ks[SKN][DH];   // 32KB
    const int tid = threadIdx.x;
    const int bh  = blockIdx.y;

    // cooperative load of K_samp
    #pragma unroll
    for (int p = 0; p < 8; p++) {
        int id = p * 256 + tid;            // 0..2047 float4s
        int s  = id >> 4;
        int d4 = (id & 15) * 4;
        int l  = (int)sidx[s];
        *(float4*)&Ks[s][d4] =
            *(const float4*)&g_K[((size_t)bh * LSEQ + l) * DH + d4];
    }
    __syncthreads();

    const int l = blockIdx.x * 256 + tid;
    float q[DH];
    const float4* Q4 = (const float4*)&g_Q[((size_t)bh * LSEQ + l) * DH];
    #pragma unroll
    for (int i = 0; i < 16; i++) {
        float4 v = Q4[i];
        q[4 * i] = v.x; q[4 * i + 1] = v.y; q[4 * i + 2] = v.z; q[4 * i + 3] = v.w;
    }

    float mx = -3.0e38f, sm = 0.0f;
    for (int s = 0; s < SKN; s++) {
        float acc = 0.0f;
        #pragma unroll
        for (int d4 = 0; d4 < 16; d4++) {
            float4 kv = *(float4*)&Ks[s][d4 * 4];
            acc += kv.x * q[4 * d4] + kv.y * q[4 * d4 + 1]
                 + kv.z * q[4 * d4 + 2] + kv.w * q[4 * d4 + 3];
        }
        mx = fmaxf(mx, acc);
        sm += acc;
    }
    g_M[bh * LSEQ + l] = mx - sm * (1.0f / SKN);
}

// ---------------- top-128 per (b,h): iterative argmax ----------------------------
__global__ void k_topk()
{
    __shared__ float vals[LSEQ];
    __shared__ float rv[256];
    __shared__ int   ri[256];
    const int tid = threadIdx.x;
    const int bh  = blockIdx.x;

    for (int i = tid; i < LSEQ; i += 256) vals[i] = g_M[bh * LSEQ + i];
    __syncthreads();

    for (int it = 0; it < TOPU; it++) {
        float bv = -3.0e38f; int bi = -1;
        #pragma unroll
        for (int j = 0; j < 16; j++) {
            int i = tid * 16 + j;
            float v = vals[i];
            if (v > bv) { bv = v; bi = i; }
        }
        rv[tid] = bv; ri[tid] = bi;
        __syncthreads();
        for (int s = 128; s > 0; s >>= 1) {
            if (tid < s) {
                float ov = rv[tid + s]; int oi = ri[tid + s];
                if (ov > rv[tid] || (ov == rv[tid] && oi < ri[tid])) {
                    rv[tid] = ov; ri[tid] = oi;
                }
            }
            __syncthreads();
        }
        if (tid == 0) {
            g_top[bh * TOPU + it] = ri[0];
            vals[ri[0]] = -3.0e38f;
        }
        __syncthreads();
    }
}

// ---------------- meanV over L per (b,h,d) ---------------------------------------
__global__ void k_meanv()
{
    __shared__ float red[256];
    const int tid  = threadIdx.x;
    const int bh   = blockIdx.x;
    const int d    = tid & 63;
    const int part = tid >> 6;

    float acc = 0.0f;
    const float* Vb = g_V + (size_t)bh * LSEQ * DH;
    for (int l = part * 1024; l < part * 1024 + 1024; l++)
        acc += Vb[(size_t)l * DH + d];
    red[tid] = acc;
    __syncthreads();
    if (tid < 64) {
        float s = red[tid] + red[tid + 64] + red[tid + 128] + red[tid + 192];
        g_meanV[bh * DH + tid] = s * (1.0f / LSEQ);
    }
}

// ---------------- broadcast-fill ctx with meanV ----------------------------------
__global__ void k_fill()
{
    size_t i = (size_t)blockIdx.x * 256 + threadIdx.x;   // float4 index
    size_t e = i * 4;
    int row = (int)(e >> 9);
    int col = (int)(e & 511);
    int b = row >> 12;              // /4096
    int h = col >> 6;
    int d = col & 63;
    float4 mv = *(const float4*)&g_meanV[(b * NH + h) * DH + d];
    *(float4*)&g_ctx[e] = mv;
}

// ---------------- top-query attention: full-L softmax·V, write into ctx ----------
__global__ void k_attn()
{
    __shared__ float q[DH];
    __shared__ float p[LSEQ];
    __shared__ float red[256];
    const int tid = threadIdx.x;
    const int u   = blockIdx.x & (TOPU - 1);
    const int bh  = blockIdx.x >> 7;
    const int lq  = g_top[bh * TOPU + u];

    if (tid < 16)
        *(float4*)&q[tid * 4] =
            *(const float4*)&g_Q[((size_t)bh * LSEQ + lq) * DH + tid * 4];
    __syncthreads();

    const float scale = 0.125f;   // 1/sqrt(64)
    const float4* K4 = (const float4*)(g_K + (size_t)bh * LSEQ * DH);

    // scores
    float lm = -3.0e38f;
    #pragma unroll 1
    for (int j = 0; j < 16; j++) {
        int l = j * 256 + tid;
        float s = 0.0f;
        #pragma unroll
        for (int d4 = 0; d4 < 16; d4++) {
            float4 kv = K4[(size_t)l * 16 + d4];
            s += kv.x * q[4 * d4] + kv.y * q[4 * d4 + 1]
               + kv.z * q[4 * d4 + 2] + kv.w * q[4 * d4 + 3];
        }
        s *= scale;
        p[l] = s;
        lm = fmaxf(lm, s);
    }
    red[tid] = lm;
    __syncthreads();
    for (int s = 128; s > 0; s >>= 1) {
        if (tid < s) red[tid] = fmaxf(red[tid], red[tid + s]);
        __syncthreads();
    }
    float m = red[0];
    __syncthreads();

    float ls = 0.0f;
    #pragma unroll 1
    for (int j = 0; j < 16; j++) {
        int l = j * 256 + tid;
        float e = __expf(p[l] - m);
        p[l] = e;
        ls += e;
    }
    red[tid] = ls;
    __syncthreads();
    for (int s = 128; s > 0; s >>= 1) {
        if (tid < s) red[tid] += red[tid + s];
        __syncthreads();
    }
    const float inv = 1.0f / red[0];
    __syncthreads();

    // ctx = p @ V
    const int d    = tid & 63;
    const int part = tid >> 6;
    const float* Vb = g_V + (size_t)bh * LSEQ * DH;
    float acc = 0.0f;
    for (int l = part * 1024; l < part * 1024 + 1024; l++)
        acc += p[l] * Vb[(size_t)l * DH + d];
    red[tid] = acc;
    __syncthreads();
    if (tid < 64) {
        float v = (red[tid] + red[tid + 64] + red[tid + 128] + red[tid + 192]) * inv;
        int b = bh >> 3, h = bh & 7;
        g_ctx[((size_t)b * LSEQ + lq) * DMOD + h * DH + tid] = v;
    }
}

// ---------------- LayerNorm (two-pass, row = 512) --------------------------------
__global__ void ln_kernel(const float* __restrict__ in,
                          const float* __restrict__ g,
                          const float* __restrict__ b,
                          float* __restrict__ out)
{
    __shared__ float sw[4];
    __shared__ float sq[4];
    const int tid  = threadIdx.x;          // 128 threads
    const int lane = tid & 31, warp = tid >> 5;
    const size_t row = blockIdx.x;

    float4 v = ((const float4*)(in + row * DMOD))[tid];
    float s = v.x + v.y + v.z + v.w;
    #pragma unroll
    for (int o = 16; o > 0; o >>= 1) s += __shfl_xor_sync(0xffffffffu, s, o);
    if (lane == 0) sw[warp] = s;
    __syncthreads();
    float mean = (sw[0] + sw[1] + sw[2] + sw[3]) * (1.0f / DMOD);

    float dx = v.x - mean, dy = v.y - mean, dz = v.z - mean, dw = v.w - mean;
    float qs = dx * dx + dy * dy + dz * dz + dw * dw;
    #pragma unroll
    for (int o = 16; o > 0; o >>= 1) qs += __shfl_xor_sync(0xffffffffu, qs, o);
    if (lane == 0) sq[warp] = qs;
    __syncthreads();
    float var = (sq[0] + sq[1] + sq[2] + sq[3]) * (1.0f / DMOD);
    float w = rsqrtf(var + 1e-6f);

    float4 gv = ((const float4*)g)[tid];
    float4 bv = ((const float4*)b)[tid];
    float4 o4 = make_float4(dx * w * gv.x + bv.x,
                            dy * w * gv.y + bv.y,
                            dz * w * gv.z + bv.z,
                            dw * w * gv.w + bv.w);
    ((float4*)(out + row * DMOD))[tid] = o4;
}

// ---------------- launch ---------------------------------------------------------
extern "C" void kernel_launch(void* const* d_in, const int* in_sizes, int n_in,
                              void* d_out, int out_size)
{
    const float* x   = (const float*)d_in[0];
    const float* Wq  = (const float*)d_in[1];
    const float* bq  = (const float*)d_in[2];
    const float* Wk  = (const float*)d_in[3];
    const float* bk  = (const float*)d_in[4];
    const float* Wv  = (const float*)d_in[5];
    const float* bvb = (const float*)d_in[6];
    const float* Wo  = (const float*)d_in[7];
    const float* bo  = (const float*)d_in[8];
    const float* g1  = (const float*)d_in[9];
    const float* b1  = (const float*)d_in[10];
    const float* W1f = (const float*)d_in[11];
    const float* b1f = (const float*)d_in[12];
    const float* W2f = (const float*)d_in[13];
    const float* b2f = (const float*)d_in[14];
    const float* g2  = (const float*)d_in[15];
    const float* b2  = (const float*)d_in[16];
    const long long* sidx = (const long long*)d_in[17];
    float* out = (float*)d_out;

    float *Q, *K, *V, *ctx, *y, *x1, *ff, *y2;
    cudaGetSymbolAddress((void**)&Q,   g_Q);
    cudaGetSymbolAddress((void**)&K,   g_K);
    cudaGetSymbolAddress((void**)&V,   g_V);
    cudaGetSymbolAddress((void**)&ctx, g_ctx);
    cudaGetSymbolAddress((void**)&y,   g_y);
    cudaGetSymbolAddress((void**)&x1,  g_x1);
    cudaGetSymbolAddress((void**)&ff,  g_ff);
    cudaGetSymbolAddress((void**)&y2,  g_y2);

    dim3 gD(DMOD / 128, ROWS / 128);   // (4, 256)
    dim3 gF(DFF  / 128, ROWS / 128);   // (16, 256)

    // QKV projections -> head-split layout
    sgemm_kernel<1,0,0><<<gD, 256>>>(x, Wq, bq, nullptr, Q, ROWS, DMOD, DMOD, LSEQ);
    sgemm_kernel<1,0,0><<<gD, 256>>>(x, Wk, bk, nullptr, K, ROWS, DMOD, DMOD, LSEQ);
    sgemm_kernel<1,0,0><<<gD, 256>>>(x, Wv, bvb, nullptr, V, ROWS, DMOD, DMOD, LSEQ);

    // sparsity measurement + top-k
    k_sample_scores<<<dim3(LSEQ / 256, BHN), 256>>>(sidx);
    k_topk<<<BHN, 256>>>();

    // meanV broadcast fill, then overwrite top queries with real attention
    k_meanv<<<BHN, 256>>>();
    k_fill<<<(ROWS * DMOD / 4) / 256, 256>>>();
    k_attn<<<BHN * TOPU, 256>>>();

    // output projection + residual, LN1
    sgemm_kernel<0,0,1><<<gD, 256>>>(ctx, Wo, bo, x, y, ROWS, DMOD, DMOD, LSEQ);
    ln_kernel<<<ROWS, 128>>>(y, g1, b1, x1);

    // FFN + residual, LN2
    sgemm_kernel<0,1,0><<<gF, 256>>>(x1, W1f, b1f, nullptr, ff, ROWS, DFF, DMOD, LSEQ);
    sgemm_kernel<0,0,1><<<gD, 256>>>(ff, W2f, b2f, x1, y2, ROWS, DMOD, DFF, LSEQ);
    ln_kernel<<<ROWS, 128>>>(y2, g2, b2, out);
}

// round 6
// speedup vs baseline: 1.5396x; 1.5396x over previous
#include <cuda_runtime.h>
#include <math.h>
#include <float.h>

// ---------------- problem constants ----------------
#define BB     8
#define LSEQ   4096
#define DMOD   512
#define DFF    2048
#define NH     8
#define DH     64
#define SKN    128
#define TOPU   128
#define ROWS   (BB*LSEQ)          // 32768
#define BHN    (BB*NH)            // 64

// ---------------- scratch (device globals; no cudaMalloc allowed) ----------------
__device__ float g_Q[(size_t)ROWS*DMOD];     // [B,H,L,DH]
__device__ float g_K[(size_t)ROWS*DMOD];     // [B,H,L,DH]
__device__ float g_V[(size_t)ROWS*DMOD];     // [B,H,L,DH]
__device__ float g_ctx[(size_t)ROWS*DMOD];   // [B,L,D]
__device__ float g_y[(size_t)ROWS*DMOD];     // x + attn_out
__device__ float g_x1[(size_t)ROWS*DMOD];    // LN1 output
__device__ float g_ff[(size_t)ROWS*DFF];     // relu(x1@W1f+b1f)
__device__ float g_y2[(size_t)ROWS*DMOD];    // x1 + ffn
__device__ float g_M[BHN*LSEQ];
__device__ int   g_top[BHN*TOPU];
__device__ float g_meanV[BHN*DH];

// ---------------- packed f32x2 helpers ----------------
__device__ __forceinline__ unsigned long long pack2(float x) {
    unsigned long long r;
    asm("mov.b64 %0, {%1, %1};" : "=l"(r) : "f"(x));
    return r;
}
__device__ __forceinline__ void fma2(unsigned long long& d,
                                     unsigned long long a,
                                     unsigned long long b) {
    asm("fma.rn.f32x2 %0, %1, %2, %0;" : "+l"(d) : "l"(a), "l"(b));
}

// ---------------- SGEMM: C[M,N] = A[M,K] @ B[K,N] + bias (+res) (relu) ----------
// PERM=1: write C in [B,H,L,DH] head-split layout (N must be 512).
template<int PERM, int RELU, int RES>
__global__ void __launch_bounds__(256, 2)
sgemm_kernel(const float* __restrict__ A, const float* __restrict__ Bm,
             const float* __restrict__ bias, const float* __restrict__ res,
             float* __restrict__ C, int M, int N, int K, int Lp)
{
    __shared__ float As[16][128];
    __shared__ float Bs[16][128];

    const int tid = threadIdx.x;
    const int tr  = tid >> 4;      // 0..15
    const int tc  = tid & 15;      // 0..15
    const int bm  = blockIdx.y * 128;
    const int bn  = blockIdx.x * 128;

    unsigned long long acc[8][4];
    #pragma unroll
    for (int m = 0; m < 8; m++)
        #pragma unroll
        for (int n = 0; n < 4; n++) acc[m][n] = 0ull;

    const float* Ab = A + (size_t)bm * K;
    const float* Bb = Bm + bn;

    for (int kt = 0; kt < K; kt += 16) {
        // load A tile (128x16), store transposed As[k][m]
        #pragma unroll
        for (int i = 0; i < 2; i++) {
            int id = tid * 2 + i;
            int r  = id >> 2;
            int c4 = (id & 3) * 4;
            float4 v = *(const float4*)(Ab + (size_t)r * K + kt + c4);
            As[c4 + 0][r] = v.x; As[c4 + 1][r] = v.y;
            As[c4 + 2][r] = v.z; As[c4 + 3][r] = v.w;
        }
        // load B tile (16x128)
        #pragma unroll
        for (int i = 0; i < 2; i++) {
            int id = tid * 2 + i;
            int r  = id >> 5;
            int c4 = (id & 31) * 4;
            *(float4*)&Bs[r][c4] = *(const float4*)(Bb + (size_t)(kt + r) * N + c4);
        }
        __syncthreads();

        #pragma unroll
        for (int kk = 0; kk < 16; kk++) {
            float4 a0 = *(float4*)&As[kk][tr * 8];
            float4 a1 = *(float4*)&As[kk][tr * 8 + 4];
            float4 b0 = *(float4*)&Bs[kk][tc * 8];
            float4 b1 = *(float4*)&Bs[kk][tc * 8 + 4];

            unsigned long long av[8];
            av[0] = pack2(a0.x); av[1] = pack2(a0.y);
            av[2] = pack2(a0.z); av[3] = pack2(a0.w);
            av[4] = pack2(a1.x); av[5] = pack2(a1.y);
            av[6] = pack2(a1.z); av[7] = pack2(a1.w);

            unsigned long long bv[4];
            bv[0] = ((const unsigned long long*)&b0)[0];
            bv[1] = ((const unsigned long long*)&b0)[1];
            bv[2] = ((const unsigned long long*)&b1)[0];
            bv[3] = ((const unsigned long long*)&b1)[1];

            #pragma unroll
            for (int m = 0; m < 8; m++)
                #pragma unroll
                for (int n = 0; n < 4; n++)
                    fma2(acc[m][n], av[m], bv[n]);
        }
        __syncthreads();
    }

    // epilogue
    const int c0 = bn + tc * 8;
    float4 bia0 = *(const float4*)(bias + c0);
    float4 bia1 = *(const float4*)(bias + c0 + 4);

    #pragma unroll
    for (int m = 0; m < 8; m++) {
        int r = bm + tr * 8 + m;
        float o[8];
        #pragma unroll
        for (int n = 0; n < 4; n++) {
            float2 f = *(float2*)&acc[m][n];
            o[2 * n]     = f.x;
            o[2 * n + 1] = f.y;
        }
        o[0] += bia0.x; o[1] += bia0.y; o[2] += bia0.z; o[3] += bia0.w;
        o[4] += bia1.x; o[5] += bia1.y; o[6] += bia1.z; o[7] += bia1.w;
        if (RES) {
            const float* rp = res + (size_t)r * N + c0;
            float4 r0 = *(const float4*)rp;
            float4 r1 = *(const float4*)(rp + 4);
            o[0] += r0.x; o[1] += r0.y; o[2] += r0.z; o[3] += r0.w;
            o[4] += r1.x; o[5] += r1.y; o[6] += r1.z; o[7] += r1.w;
        }
        if (RELU) {
            #pragma unroll
            for (int j = 0; j < 8; j++) o[j] = fmaxf(o[j], 0.0f);
        }
        float4 w0 = make_float4(o[0], o[1], o[2], o[3]);
        float4 w1 = make_float4(o[4], o[5], o[6], o[7]);
        if (PERM) {
            int b = r / Lp, l = r - b * Lp;
            int h = c0 >> 6, d = c0 & 63;
            float* cp = C + (((size_t)(b * NH + h) * Lp + l) << 6) + d;
            *(float4*)cp = w0;
            *(float4*)(cp + 4) = w1;
        } else {
            float* cp = C + (size_t)r * N + c0;
            *(float4*)cp = w0;
            *(float4*)(cp + 4) = w1;
        }
    }
}

// ---------------- sampled scores: M[bh,l] = max_s(q.ks) - mean_s(q.ks) -----------
__global__ void k_sample_scores(const long long* __restrict__ sidx)
{
    __shared__ float Ks[SKN][DH];   // 32KB
    const int tid = threadIdx.x;
    const int bh  = blockIdx.y;

    // cooperative load of K_samp
    #pragma unroll
    for (int p = 0; p < 8; p++) {
        int id = p * 256 + tid;            // 0..2047 float4s
        int s  = id >> 4;
        int d4 = (id & 15) * 4;
        int l  = (int)sidx[s];
        *(float4*)&Ks[s][d4] =
            *(const float4*)&g_K[((size_t)bh * LSEQ + l) * DH + d4];
    }
    __syncthreads();

    const int l = blockIdx.x * 256 + tid;
    float q[DH];
    const float4* Q4 = (const float4*)&g_Q[((size_t)bh * LSEQ + l) * DH];
    #pragma unroll
    for (int i = 0; i < 16; i++) {
        float4 v = Q4[i];
        q[4 * i] = v.x; q[4 * i + 1] = v.y; q[4 * i + 2] = v.z; q[4 * i + 3] = v.w;
    }

    float mx = -3.0e38f, sm = 0.0f;
    for (int s = 0; s < SKN; s++) {
        float acc = 0.0f;
        #pragma unroll
        for (int d4 = 0; d4 < 16; d4++) {
            float4 kv = *(float4*)&Ks[s][d4 * 4];
            acc += kv.x * q[4 * d4] + kv.y * q[4 * d4 + 1]
                 + kv.z * q[4 * d4 + 2] + kv.w * q[4 * d4 + 3];
        }
        mx = fmaxf(mx, acc);
        sm += acc;
    }
    g_M[bh * LSEQ + l] = mx - sm * (1.0f / SKN);
}

// ---------------- top-128 per (b,h): iterative argmax ----------------------------
__global__ void k_topk()
{
    __shared__ float vals[LSEQ];
    __shared__ float rv[256];
    __shared__ int   ri[256];
    const int tid = threadIdx.x;
    const int bh  = blockIdx.x;

    for (int i = tid; i < LSEQ; i += 256) vals[i] = g_M[bh * LSEQ + i];
    __syncthreads();

    for (int it = 0; it < TOPU; it++) {
        float bv = -3.0e38f; int bi = -1;
        #pragma unroll
        for (int j = 0; j < 16; j++) {
            int i = tid * 16 + j;
            float v = vals[i];
            if (v > bv) { bv = v; bi = i; }
        }
        rv[tid] = bv; ri[tid] = bi;
        __syncthreads();
        for (int s = 128; s > 0; s >>= 1) {
            if (tid < s) {
                float ov = rv[tid + s]; int oi = ri[tid + s];
                if (ov > rv[tid] || (ov == rv[tid] && oi < ri[tid])) {
                    rv[tid] = ov; ri[tid] = oi;
                }
            }
            __syncthreads();
        }
        if (tid == 0) {
            g_top[bh * TOPU + it] = ri[0];
            vals[ri[0]] = -3.0e38f;
        }
        __syncthreads();
    }
}

// ---------------- meanV over L per (b,h,d) ---------------------------------------
__global__ void k_meanv()
{
    __shared__ float red[256];
    const int tid  = threadIdx.x;
    const int bh   = blockIdx.x;
    const int d    = tid & 63;
    const int part = tid >> 6;

    float acc = 0.0f;
    const float* Vb = g_V + (size_t)bh * LSEQ * DH;
    for (int l = part * 1024; l < part * 1024 + 1024; l++)
        acc += Vb[(size_t)l * DH + d];
    red[tid] = acc;
    __syncthreads();
    if (tid < 64) {
        float s = red[tid] + red[tid + 64] + red[tid + 128] + red[tid + 192];
        g_meanV[bh * DH + tid] = s * (1.0f / LSEQ);
    }
}

// ---------------- broadcast-fill ctx with meanV ----------------------------------
__global__ void k_fill()
{
    size_t i = (size_t)blockIdx.x * 256 + threadIdx.x;   // float4 index
    size_t e = i * 4;
    int row = (int)(e >> 9);
    int col = (int)(e & 511);
    int b = row >> 12;              // /4096
    int h = col >> 6;
    int d = col & 63;
    float4 mv = *(const float4*)&g_meanV[(b * NH + h) * DH + d];
    *(float4*)&g_ctx[e] = mv;
}

// ---------------- top-query attention: full-L softmax·V, write into ctx ----------
__global__ void k_attn()
{
    __shared__ float q[DH];
    __shared__ float p[LSEQ];
    __shared__ float red[256];
    const int tid = threadIdx.x;
    const int u   = blockIdx.x & (TOPU - 1);
    const int bh  = blockIdx.x >> 7;
    const int lq  = g_top[bh * TOPU + u];

    if (tid < 16)
        *(float4*)&q[tid * 4] =
            *(const float4*)&g_Q[((size_t)bh * LSEQ + lq) * DH + tid * 4];
    __syncthreads();

    const float scale = 0.125f;   // 1/sqrt(64)
    const float4* K4 = (const float4*)(g_K + (size_t)bh * LSEQ * DH);

    // scores
    float lm = -3.0e38f;
    #pragma unroll 1
    for (int j = 0; j < 16; j++) {
        int l = j * 256 + tid;
        float s = 0.0f;
        #pragma unroll
        for (int d4 = 0; d4 < 16; d4++) {
            float4 kv = K4[(size_t)l * 16 + d4];
            s += kv.x * q[4 * d4] + kv.y * q[4 * d4 + 1]
               + kv.z * q[4 * d4 + 2] + kv.w * q[4 * d4 + 3];
        }
        s *= scale;
        p[l] = s;
        lm = fmaxf(lm, s);
    }
    red[tid] = lm;
    __syncthreads();
    for (int s = 128; s > 0; s >>= 1) {
        if (tid < s) red[tid] = fmaxf(red[tid], red[tid + s]);
        __syncthreads();
    }
    float m = red[0];
    __syncthreads();

    float ls = 0.0f;
    #pragma unroll 1
    for (int j = 0; j < 16; j++) {
        int l = j * 256 + tid;
        float e = __expf(p[l] - m);
        p[l] = e;
        ls += e;
    }
    red[tid] = ls;
    __syncthreads();
    for (int s = 128; s > 0; s >>= 1) {
        if (tid < s) red[tid] += red[tid + s];
        __syncthreads();
    }
    const float inv = 1.0f / red[0];
    __syncthreads();

    // ctx = p @ V
    const int d    = tid & 63;
    const int part = tid >> 6;
    const float* Vb = g_V + (size_t)bh * LSEQ * DH;
    float acc = 0.0f;
    for (int l = part * 1024; l < part * 1024 + 1024; l++)
        acc += p[l] * Vb[(size_t)l * DH + d];
    red[tid] = acc;
    __syncthreads();
    if (tid < 64) {
        float v = (red[tid] + red[tid + 64] + red[tid + 128] + red[tid + 192]) * inv;
        int b = bh >> 3, h = bh & 7;
        g_ctx[((size_t)b * LSEQ + lq) * DMOD + h * DH + tid] = v;
    }
}

// ---------------- LayerNorm (two-pass, row = 512) --------------------------------
__global__ void ln_kernel(const float* __restrict__ in,
                          const float* __restrict__ g,
                          const float* __restrict__ b,
                          float* __restrict__ out)
{
    __shared__ float sw[4];
    __shared__ float sq[4];
    const int tid  = threadIdx.x;          // 128 threads
    const int lane = tid & 31, warp = tid >> 5;
    const size_t row = blockIdx.x;

    float4 v = ((const float4*)(in + row * DMOD))[tid];
    float s = v.x + v.y + v.z + v.w;
    #pragma unroll
    for (int o = 16; o > 0; o >>= 1) s += __shfl_xor_sync(0xffffffffu, s, o);
    if (lane == 0) sw[warp] = s;
    __syncthreads();
    float mean = (sw[0] + sw[1] + sw[2] + sw[3]) * (1.0f / DMOD);

    float dx = v.x - mean, dy = v.y - mean, dz = v.z - mean, dw = v.w - mean;
    float qs = dx * dx + dy * dy + dz * dz + dw * dw;
    #pragma unroll
    for (int o = 16; o > 0; o >>= 1) qs += __shfl_xor_sync(0xffffffffu, qs, o);
    if (lane == 0) sq[warp] = qs;
    __syncthreads();
    float var = (sq[0] + sq[1] + sq[2] + sq[3]) * (1.0f / DMOD);
    float w = rsqrtf(var + 1e-6f);

    float4 gv = ((const float4*)g)[tid];
    float4 bv = ((const float4*)b)[tid];
    float4 o4 = make_float4(dx * w * gv.x + bv.x,
                            dy * w * gv.y + bv.y,
                            dz * w * gv.z + bv.z,
                            dw * w * gv.w + bv.w);
    ((float4*)(out + row * DMOD))[tid] = o4;
}

// ---------------- launch ---------------------------------------------------------
extern "C" void kernel_launch(void* const* d_in, const int* in_sizes, int n_in,
                              void* d_out, int out_size)
{
    const float* x   = (const float*)d_in[0];
    const float* Wq  = (const float*)d_in[1];
    const float* bq  = (const float*)d_in[2];
    const float* Wk  = (const float*)d_in[3];
    const float* bk  = (const float*)d_in[4];
    const float* Wv  = (const float*)d_in[5];
    const float* bvb = (const float*)d_in[6];
    const float* Wo  = (const float*)d_in[7];
    const float* bo  = (const float*)d_in[8];
    const float* g1  = (const float*)d_in[9];
    const float* b1  = (const float*)d_in[10];
    const float* W1f = (const float*)d_in[11];
    const float* b1f = (const float*)d_in[12];
    const float* W2f = (const float*)d_in[13];
    const float* b2f = (const float*)d_in[14];
    const float* g2  = (const float*)d_in[15];
    const float* b2  = (const float*)d_in[16];
    const long long* sidx = (const long long*)d_in[17];
    float* out = (float*)d_out;

    float *Q, *K, *V, *ctx, *y, *x1, *ff, *y2;
    cudaGetSymbolAddress((void**)&Q,   g_Q);
    cudaGetSymbolAddress((void**)&K,   g_K);
    cudaGetSymbolAddress((void**)&V,   g_V);
    cudaGetSymbolAddress((void**)&ctx, g_ctx);
    cudaGetSymbolAddress((void**)&y,   g_y);
    cudaGetSymbolAddress((void**)&x1,  g_x1);
    cudaGetSymbolAddress((void**)&ff,  g_ff);
    cudaGetSymbolAddress((void**)&y2,  g_y2);

    dim3 gD(DMOD / 128, ROWS / 128);   // (4, 256)
    dim3 gF(DFF  / 128, ROWS / 128);   // (16, 256)

    // QKV projections -> head-split layout
    sgemm_kernel<1,0,0><<<gD, 256>>>(x, Wq, bq, nullptr, Q, ROWS, DMOD, DMOD, LSEQ);
    sgemm_kernel<1,0,0><<<gD, 256>>>(x, Wk, bk, nullptr, K, ROWS, DMOD, DMOD, LSEQ);
    sgemm_kernel<1,0,0><<<gD, 256>>>(x, Wv, bvb, nullptr, V, ROWS, DMOD, DMOD, LSEQ);

    // sparsity measurement + top-k
    k_sample_scores<<<dim3(LSEQ / 256, BHN), 256>>>(sidx);
    k_topk<<<BHN, 256>>>();

    // meanV broadcast fill, then overwrite top queries with real attention
    k_meanv<<<BHN, 256>>>();
    k_fill<<<(ROWS * DMOD / 4) / 256, 256>>>();
    k_attn<<<BHN * TOPU, 256>>>();

    // output projection + residual, LN1
    sgemm_kernel<0,0,1><<<gD, 256>>>(ctx, Wo, bo, x, y, ROWS, DMOD, DMOD, LSEQ);
    ln_kernel<<<ROWS, 128>>>(y, g1, b1, x1);

    // FFN + residual, LN2
    sgemm_kernel<0,1,0><<<gF, 256>>>(x1, W1f, b1f, nullptr, ff, ROWS, DFF, DMOD, LSEQ);
    sgemm_kernel<0,0,1><<<gD, 256>>>(ff, W2f, b2f, x1, y2, ROWS, DMOD, DFF, LSEQ);
    ln_kernel<<<ROWS, 128>>>(y2, g2, b2, out);
}